// round 6
// baseline (speedup 1.0000x reference)
#include <cuda_runtime.h>

// Problem constants (shapes fixed by the dataset)
#define UQ 100000          // users
#define MQ 50000           // movies
#define HH 64              // hidden dim
#define UN (UQ*HH)
#define MN (MQ*HH)
#define PAD_U 64           // max user degree slots (Poisson(20) tail safe)
#define PAD_M 128          // max movie degree slots (Poisson(40) tail safe)

// Scratch layout inside one big __device__ buffer (offsets in floats)
#define OFF_XU0  0
#define OFF_XU1  (OFF_XU0 + UN)
#define OFF_XM0  (OFF_XU1 + UN)
#define OFF_XM1  (OFF_XM0 + MN)
#define OFF_AGGU (OFF_XM1 + MN)
#define OFF_AGGM (OFF_AGGU + UN)
#define TOTAL_F  (OFF_AGGM + MN)

__device__ __align__(16) float g_buf[TOTAL_F];        // ~115 MB scratch
__device__ int g_deg[UQ + MQ];                        // users then movies (fill cursors)
__device__ __align__(16) int g_bucket_u[UQ * PAD_U];  // movie ids per user
__device__ __align__(16) int g_bucket_m[MQ * PAD_M];  // user ids per movie

// ---------------------------------------------------------------------------
__global__ void k_zero_deg(int n) {
    int i = blockIdx.x * blockDim.x + threadIdx.x;
    if (i < n) g_deg[i] = 0;
}

// Fused init: movie blocks compute x_m0 = movie_x @ W.T + b + movie_emb
// (4 rows/block, 256 thr); user blocks copy user_emb into g_buf.
__global__ void __launch_bounds__(256)
k_init(const float4* __restrict__ uemb,
       const float* __restrict__ mx, const float* __restrict__ w,
       const float* __restrict__ b, const float* __restrict__ memb,
       int MB4, int M, int U) {
    int tid = threadIdx.x;
    if ((int)blockIdx.x < MB4) {
        __shared__ float xs[4][20];
        int r = tid >> 6, o = tid & 63;
        int row = blockIdx.x * 4 + r;
        if (tid < 80) {
            int rr = tid / 20, cc = tid % 20;
            int g = blockIdx.x * 4 + rr;
            if (g < M) xs[rr][cc] = __ldg(mx + g * 20 + cc);
        }
        __syncthreads();
        if (row < M) {
            float acc = __ldg(b + o) + __ldg(memb + row * 64 + o);
#pragma unroll
            for (int k = 0; k < 20; k++) acc = fmaf(xs[r][k], __ldg(w + o * 20 + k), acc);
            g_buf[OFF_XM0 + row * 64 + o] = acc;
        }
    } else {
        int i = ((int)blockIdx.x - MB4) * 256 + tid;
        if (i < U * 16) ((float4*)(g_buf + OFF_XU0))[i] = __ldg(uemb + i);
    }
}

// Bucket fill: degree counting and slot allocation in one pass over edges.
__global__ void k_fill(const int* __restrict__ es, const int* __restrict__ ed, int E) {
    int e = blockIdx.x * blockDim.x + threadIdx.x;
    if (e >= E) return;
    int u = __ldg(es + e), m = __ldg(ed + e);
    int su = atomicAdd(&g_deg[u], 1);
    if (su < PAD_U) g_bucket_u[u * PAD_U + su] = m;
    int sm = atomicAdd(&g_deg[UQ + m], 1);
    if (sm < PAD_M) g_bucket_m[m * PAD_M + sm] = u;
}

// ---------------------------------------------------------------------------
// Gather-mean (round-2 proven structure + inline inverse degree).
// 16 lanes per node, fp32 rows, unroll 4.
// which=1: movies aggregate user rows; which=0: users aggregate movie rows.
__global__ void k_gather(int which, int x_off, int out_off, int n_nodes) {
    int t = blockIdx.x * blockDim.x + threadIdx.x;
    int node = t >> 4;
    if (node >= n_nodes) return;
    int lane = t & 15;
    const int pad      = which ? PAD_M : PAD_U;
    const int* bucket  = which ? g_bucket_m : g_bucket_u;
    const int degbase  = which ? UQ : 0;

    const float4* x = (const float4*)(g_buf + x_off);
    const int* bk = bucket + (long)node * pad;
    int dt = g_deg[degbase + node];
    float iv = 1.f / fmaxf((float)dt, 1.f);
    int d = min(dt, pad);

    float4 acc = make_float4(0.f, 0.f, 0.f, 0.f);
    int i = 0;
    for (; i + 4 <= d; i += 4) {
        int4 nb = __ldg((const int4*)(bk + i));
        float4 v0 = __ldg(x + nb.x * 16 + lane);
        float4 v1 = __ldg(x + nb.y * 16 + lane);
        float4 v2 = __ldg(x + nb.z * 16 + lane);
        float4 v3 = __ldg(x + nb.w * 16 + lane);
        acc.x += (v0.x + v1.x) + (v2.x + v3.x);
        acc.y += (v0.y + v1.y) + (v2.y + v3.y);
        acc.z += (v0.z + v1.z) + (v2.z + v3.z);
        acc.w += (v0.w + v1.w) + (v2.w + v3.w);
    }
    for (; i < d; i++) {
        int nb = __ldg(bk + i);
        float4 v = __ldg(x + nb * 16 + lane);
        acc.x += v.x; acc.y += v.y; acc.z += v.z; acc.w += v.w;
    }
    acc.x *= iv; acc.y *= iv; acc.z *= iv; acc.w *= iv;
    ((float4*)(g_buf + out_off))[node * 16 + lane] = acc;
}

// ---------------------------------------------------------------------------
// Node update (round-2 proven): x_new = mean @ Wl^T + bl + x_old @ Wr^T (+relu).
// 256 threads, 16 rows/block; thread = 2 rows x 2 outputs; pad-66 smem weights.
#define UROWS 16
__global__ void __launch_bounds__(256)
k_update(int agg_off, int xold_off, int xnew_off,
         const float* __restrict__ wl, const float* __restrict__ bl,
         const float* __restrict__ wr, int nrows, int do_relu) {
    __shared__ float wls[64 * 66];
    __shared__ float wrs[64 * 66];
    __shared__ float rs[UROWS][128];
    int tid = threadIdx.x;

    for (int idx = tid; idx < 4096; idx += 256) {
        int o = idx >> 6, i = idx & 63;
        wls[i * 66 + o] = __ldg(wl + idx);
        wrs[i * 66 + o] = __ldg(wr + idx);
    }
    int row0 = blockIdx.x * UROWS;
    const float4* agg4 = (const float4*)(g_buf + agg_off);
    const float4* xo4  = (const float4*)(g_buf + xold_off);
    for (int idx = tid; idx < UROWS * 16; idx += 256) {
        int r = idx >> 4, q = idx & 15;
        int g = row0 + r;
        if (g < nrows) {
            *(float4*)&rs[r][q * 4]      = (q < 16) ? __ldg(agg4 + g * 16 + (q & 15))
                                                    : make_float4(0,0,0,0);
        }
    }
    // second half: x_old
    for (int idx = tid; idx < UROWS * 16; idx += 256) {
        int r = idx >> 4, q = idx & 15;
        int g = row0 + r;
        if (g < nrows) {
            *(float4*)&rs[r][64 + q * 4] = __ldg(xo4 + g * 16 + q);
        }
    }
    __syncthreads();

    int lane = tid & 31, wrp = tid >> 5;
    int r0 = wrp * 2;                 // 8 warps x 2 rows = 16 rows
    int o0 = lane * 2;                // 32 lanes x 2 outputs = 64 outputs
    float b0 = __ldg(bl + o0), b1 = __ldg(bl + o0 + 1);
    float a00 = b0, a01 = b1, a10 = b0, a11 = b1;

#pragma unroll 16
    for (int i = 0; i < 64; i++) {
        float2 wlv = *(const float2*)&wls[i * 66 + o0];
        float2 wrv = *(const float2*)&wrs[i * 66 + o0];
        float m0 = rs[r0][i],     x0 = rs[r0][64 + i];
        float m1 = rs[r0 + 1][i], x1 = rs[r0 + 1][64 + i];
        a00 = fmaf(m0, wlv.x, fmaf(x0, wrv.x, a00));
        a01 = fmaf(m0, wlv.y, fmaf(x0, wrv.y, a01));
        a10 = fmaf(m1, wlv.x, fmaf(x1, wrv.x, a10));
        a11 = fmaf(m1, wlv.y, fmaf(x1, wrv.y, a11));
    }
    if (do_relu) {
        a00 = fmaxf(a00, 0.f); a01 = fmaxf(a01, 0.f);
        a10 = fmaxf(a10, 0.f); a11 = fmaxf(a11, 0.f);
    }
    float* xnew = g_buf + xnew_off;
    int g0 = row0 + r0;
    if (g0 < nrows)     ((float2*)(xnew + g0 * 64))[lane]       = make_float2(a00, a01);
    if (g0 + 1 < nrows) ((float2*)(xnew + (g0 + 1) * 64))[lane] = make_float2(a10, a11);
}

// out[l] = dot(x_u[label_src[l]], x_m[label_dst[l]]); one warp per label.
__global__ void k_labels(const int* __restrict__ ls, const int* __restrict__ ld,
                         int xu_off, int xm_off, float* __restrict__ out, int L) {
    int t = blockIdx.x * blockDim.x + threadIdx.x;
    int l = t >> 5;
    if (l >= L) return;
    int lane = t & 31;
    const float2* xu = (const float2*)(g_buf + xu_off);
    const float2* xm = (const float2*)(g_buf + xm_off);
    int s = __ldg(ls + l), d = __ldg(ld + l);
    float2 a = __ldg(xu + s * 32 + lane);
    float2 b = __ldg(xm + d * 32 + lane);
    float v = fmaf(a.x, b.x, a.y * b.y);
#pragma unroll
    for (int off = 16; off; off >>= 1) v += __shfl_xor_sync(0xffffffffu, v, off);
    if (lane == 0) out[l] = v;
}

// ---------------------------------------------------------------------------
extern "C" void kernel_launch(void* const* d_in, const int* in_sizes, int n_in,
                              void* d_out, int out_size) {
    const float* movie_x   = (const float*)d_in[0];
    const float* user_emb  = (const float*)d_in[1];
    const float* movie_emb = (const float*)d_in[2];
    const float* mw        = (const float*)d_in[3];
    const float* mb        = (const float*)d_in[4];
    const float* wl        = (const float*)d_in[5];
    const float* blb       = (const float*)d_in[6];
    const float* wr        = (const float*)d_in[7];
    const int*   es        = (const int*)d_in[8];
    const int*   ed        = (const int*)d_in[9];
    const int*   ls        = (const int*)d_in[10];
    const int*   ld        = (const int*)d_in[11];
    float* out = (float*)d_out;

    const int U = in_sizes[1] / HH;
    const int M = in_sizes[2] / HH;
    const int E = in_sizes[8];
    const int L = in_sizes[10];
    const int TB = 256;

    // launch 0: zero degree counters
    k_zero_deg<<<(U + M + TB - 1) / TB, TB>>>(U + M);
    // launch 1: fused feature init (movies projected, users copied)
    const int MB4 = (M + 3) / 4;
    const int UBc = (U * 16 + TB - 1) / TB;
    k_init<<<MB4 + UBc, TB>>>((const float4*)user_emb, movie_x, mw, mb, movie_emb,
                              MB4, M, U);
    // launch 2: adjacency buckets (+degree counting)
    k_fill<<<(E + TB - 1) / TB, TB>>>(es, ed, E);

    for (int layer = 0; layer < 2; layer++) {
        const int xu_in  = layer ? OFF_XU1 : OFF_XU0;
        const int xm_in  = layer ? OFF_XM1 : OFF_XM0;
        const int xu_out = layer ? OFF_XU0 : OFF_XU1;
        const int xm_out = layer ? OFF_XM0 : OFF_XM1;

        // launch 3 (profiled on layer 0): movie gather — the hot kernel
        k_gather<<<(M * 16 + TB - 1) / TB, TB>>>(1, xu_in, OFF_AGGM, M);
        k_gather<<<(U * 16 + TB - 1) / TB, TB>>>(0, xm_in, OFF_AGGU, U);

        const float* wl0 = wl  + (layer * 2 + 0) * 4096;
        const float* bl0 = blb + (layer * 2 + 0) * 64;
        const float* wr0 = wr  + (layer * 2 + 0) * 4096;
        k_update<<<(M + UROWS - 1) / UROWS, 256>>>(OFF_AGGM, xm_in, xm_out,
                                                   wl0, bl0, wr0, M, layer == 0);
        const float* wl1 = wl  + (layer * 2 + 1) * 4096;
        const float* bl1 = blb + (layer * 2 + 1) * 64;
        const float* wr1 = wr  + (layer * 2 + 1) * 4096;
        k_update<<<(U + UROWS - 1) / UROWS, 256>>>(OFF_AGGU, xu_in, xu_out,
                                                   wl1, bl1, wr1, U, layer == 0);
    }

    // final features are in the *0 buffers
    long lt = (long)L * 32;
    k_labels<<<(int)((lt + TB - 1) / TB), TB>>>(ls, ld, OFF_XU0, OFF_XM0, out, L);
}

// round 7
// speedup vs baseline: 1.6944x; 1.6944x over previous
#include <cuda_runtime.h>
#include <cuda_fp16.h>

// Problem constants (shapes fixed by the dataset)
#define UQ 100000          // users
#define MQ 50000           // movies
#define HH 64              // hidden dim
#define UN (UQ*HH)
#define MN (MQ*HH)
#define PAD_U 64           // max user degree slots (Poisson(20) tail safe)
#define PAD_M 128          // max movie degree slots (Poisson(40) tail safe)

// Scratch layout inside one big __device__ buffer (offsets in floats)
#define OFF_XU0  0
#define OFF_XU1  (OFF_XU0 + UN)
#define OFF_XM0  (OFF_XU1 + UN)
#define OFF_XM1  (OFF_XM0 + MN)
#define OFF_ZU   (OFF_XM1 + MN)      // z_u = x_u @ Wr^T + b   [U,64] fp32
#define OFF_ZM   (OFF_ZU + UN)       // z_m = x_m @ Wr^T + b   [M,64] fp32
#define TOTAL_F  (OFF_ZM + MN)

__device__ __align__(16) float g_buf[TOTAL_F];        // ~115 MB scratch
__device__ int g_deg[UQ + MQ];                        // users then movies (fill cursors)
__device__ __align__(16) int g_bucket_u[UQ * PAD_U];  // movie ids per user
__device__ __align__(16) int g_bucket_m[MQ * PAD_M];  // user ids per movie
__device__ __align__(16) __half g_hyu[UN];            // y_u = x_u @ Wl[l,0]^T (fp16)
__device__ __align__(16) __half g_hym[MN];            // y_m = x_m @ Wl[l,1]^T (fp16)

// ---------------------------------------------------------------------------
__global__ void k_zero_deg(int n) {
    int i = blockIdx.x * blockDim.x + threadIdx.x;
    if (i < n) g_deg[i] = 0;
}

// Fused init: movie blocks compute x_m0 = movie_x @ W.T + b + movie_emb
// (4 rows/block, 256 thr); user blocks copy user_emb into g_buf.
__global__ void __launch_bounds__(256)
k_init(const float4* __restrict__ uemb,
       const float* __restrict__ mx, const float* __restrict__ w,
       const float* __restrict__ b, const float* __restrict__ memb,
       int MB4, int M, int U) {
    int tid = threadIdx.x;
    if ((int)blockIdx.x < MB4) {
        __shared__ float xs[4][20];
        int r = tid >> 6, o = tid & 63;
        int row = blockIdx.x * 4 + r;
        if (tid < 80) {
            int rr = tid / 20, cc = tid % 20;
            int g = blockIdx.x * 4 + rr;
            if (g < M) xs[rr][cc] = __ldg(mx + g * 20 + cc);
        }
        __syncthreads();
        if (row < M) {
            float acc = __ldg(b + o) + __ldg(memb + row * 64 + o);
#pragma unroll
            for (int k = 0; k < 20; k++) acc = fmaf(xs[r][k], __ldg(w + o * 20 + k), acc);
            g_buf[OFF_XM0 + row * 64 + o] = acc;
        }
    } else {
        int i = ((int)blockIdx.x - MB4) * 256 + tid;
        if (i < U * 16) ((float4*)(g_buf + OFF_XU0))[i] = __ldg(uemb + i);
    }
}

// Bucket fill: degree counting and slot allocation in one pass over edges.
__global__ void k_fill(const int* __restrict__ es, const int* __restrict__ ed, int E) {
    int e = blockIdx.x * blockDim.x + threadIdx.x;
    if (e >= E) return;
    int u = __ldg(es + e), m = __ldg(ed + e);
    int su = atomicAdd(&g_deg[u], 1);
    if (su < PAD_U) g_bucket_u[u * PAD_U + su] = m;
    int sm = atomicAdd(&g_deg[UQ + m], 1);
    if (sm < PAD_M) g_bucket_m[m * PAD_M + sm] = u;
}

// ---------------------------------------------------------------------------
// Pre-transform (dense, per node): y = x @ Wl_y^T (fp16, feeds the gather),
// z = x @ Wr_z^T + b (fp32, dst-side term). One launch over movies then users.
// 256 threads, 16 rows/block; thread = 2 rows x 2 outputs (round-2 proven tile).
#define PROWS 16
__global__ void __launch_bounds__(256)
k_pre(int xm_off, int xu_off, const float* __restrict__ wl,
      const float* __restrict__ bl, const float* __restrict__ wr,
      int layer, int MBLK, int M, int U) {
    __shared__ float wsy[64 * 66];        // Wl_y transposed [i][o]
    __shared__ float wsz[64 * 66];        // Wr_z transposed [i][o]
    __shared__ float rs[PROWS][68];       // x rows
    const bool is_movie = (int)blockIdx.x < MBLK;
    // movies: y feeds user-dst edges (et=1); z is dst term of movie-dst edges (et=0)
    const int et_y = is_movie ? 1 : 0;
    const int et_z = is_movie ? 0 : 1;
    const float* wly = wl + (layer * 2 + et_y) * 4096;
    const float* wrz = wr + (layer * 2 + et_z) * 4096;
    const float* blz = bl + (layer * 2 + et_z) * 64;
    const int nrows = is_movie ? M : U;
    const int x_off = is_movie ? xm_off : xu_off;
    const int z_off = is_movie ? OFF_ZM : OFF_ZU;
    __half* ytab    = is_movie ? g_hym : g_hyu;
    const int row0  = (is_movie ? blockIdx.x : blockIdx.x - MBLK) * PROWS;
    int tid = threadIdx.x;

    for (int idx = tid; idx < 4096; idx += 256) {
        int o = idx >> 6, i = idx & 63;
        wsy[i * 66 + o] = __ldg(wly + idx);
        wsz[i * 66 + o] = __ldg(wrz + idx);
    }
    const float4* x4 = (const float4*)(g_buf + x_off);
    {
        int r = tid >> 4, q = tid & 15;   // 256 threads = 16 rows x 16 quads
        int g = row0 + r;
        if (g < nrows) *(float4*)&rs[r][q * 4] = __ldg(x4 + g * 16 + q);
    }
    __syncthreads();

    int lane = tid & 31, wrp = tid >> 5;
    int r0 = wrp * 2;                 // 8 warps x 2 rows = 16 rows
    int o0 = lane * 2;                // 32 lanes x 2 outputs = 64 outputs
    float zb0 = __ldg(blz + o0), zb1 = __ldg(blz + o0 + 1);
    float y00 = 0.f, y01 = 0.f, y10 = 0.f, y11 = 0.f;
    float z00 = zb0, z01 = zb1, z10 = zb0, z11 = zb1;

#pragma unroll 16
    for (int i = 0; i < 64; i++) {
        float2 wy = *(const float2*)&wsy[i * 66 + o0];
        float2 wz = *(const float2*)&wsz[i * 66 + o0];
        float x0 = rs[r0][i], x1 = rs[r0 + 1][i];
        y00 = fmaf(x0, wy.x, y00); y01 = fmaf(x0, wy.y, y01);
        y10 = fmaf(x1, wy.x, y10); y11 = fmaf(x1, wy.y, y11);
        z00 = fmaf(x0, wz.x, z00); z01 = fmaf(x0, wz.y, z01);
        z10 = fmaf(x1, wz.x, z10); z11 = fmaf(x1, wz.y, z11);
    }
    float* z = g_buf + z_off;
    int g0 = row0 + r0;
    if (g0 < nrows) {
        ((float2*)(z + g0 * 64))[lane] = make_float2(z00, z01);
        ((__half2*)(ytab + g0 * 64))[lane] = __floats2half2_rn(y00, y01);
    }
    if (g0 + 1 < nrows) {
        ((float2*)(z + (g0 + 1) * 64))[lane] = make_float2(z10, z11);
        ((__half2*)(ytab + (g0 + 1) * 64))[lane] = __floats2half2_rn(y10, y11);
    }
}

// ---------------------------------------------------------------------------
__device__ __forceinline__ void acc8(float* a, uint4 v) {
    float2 f;
    f = __half22float2(*(__half2*)&v.x); a[0] += f.x; a[1] += f.y;
    f = __half22float2(*(__half2*)&v.y); a[2] += f.x; a[3] += f.y;
    f = __half22float2(*(__half2*)&v.z); a[4] += f.x; a[5] += f.y;
    f = __half22float2(*(__half2*)&v.w); a[6] += f.x; a[7] += f.y;
}

// Gather-mean of fp16 y rows + z + optional relu -> x_new (fp32).
// 8 lanes per node (y row = 128 B = one cache line). Movies [0,M), users [M,M+U).
__global__ void k_gather_add(int xm_out, int xu_out, int M, int U, int do_relu) {
    int t = blockIdx.x * blockDim.x + threadIdx.x;
    int node = t >> 3;
    if (node >= M + U) return;
    int lane = t & 7;
    bool is_movie = node < M;
    int local = is_movie ? node : node - M;
    const int pad = is_movie ? PAD_M : PAD_U;
    const int* bk = (is_movie ? g_bucket_m : g_bucket_u) + (long)local * pad;
    int dt = g_deg[(is_movie ? UQ : 0) + local];
    float iv = 1.f / fmaxf((float)dt, 1.f);
    int d = min(dt, pad);
    const uint4* y4 = (const uint4*)(is_movie ? g_hyu : g_hym);  // gather OTHER side's y

    float a[8] = {0.f, 0.f, 0.f, 0.f, 0.f, 0.f, 0.f, 0.f};
    int i = 0;
    for (; i + 4 <= d; i += 4) {
        int4 nb = __ldg((const int4*)(bk + i));
        uint4 v0 = __ldg(y4 + nb.x * 8 + lane);
        uint4 v1 = __ldg(y4 + nb.y * 8 + lane);
        uint4 v2 = __ldg(y4 + nb.z * 8 + lane);
        uint4 v3 = __ldg(y4 + nb.w * 8 + lane);
        acc8(a, v0); acc8(a, v1); acc8(a, v2); acc8(a, v3);
    }
    for (; i < d; i++) {
        int nb = __ldg(bk + i);
        acc8(a, __ldg(y4 + nb * 8 + lane));
    }
    const float4* zp = (const float4*)(g_buf + (is_movie ? OFF_ZM : OFF_ZU)) + local * 16 + lane * 2;
    float4 z0 = __ldg(zp), z1 = __ldg(zp + 1);
    float4 r0 = make_float4(fmaf(a[0], iv, z0.x), fmaf(a[1], iv, z0.y),
                            fmaf(a[2], iv, z0.z), fmaf(a[3], iv, z0.w));
    float4 r1 = make_float4(fmaf(a[4], iv, z1.x), fmaf(a[5], iv, z1.y),
                            fmaf(a[6], iv, z1.z), fmaf(a[7], iv, z1.w));
    if (do_relu) {
        r0.x = fmaxf(r0.x, 0.f); r0.y = fmaxf(r0.y, 0.f);
        r0.z = fmaxf(r0.z, 0.f); r0.w = fmaxf(r0.w, 0.f);
        r1.x = fmaxf(r1.x, 0.f); r1.y = fmaxf(r1.y, 0.f);
        r1.z = fmaxf(r1.z, 0.f); r1.w = fmaxf(r1.w, 0.f);
    }
    float4* o4 = (float4*)(g_buf + (is_movie ? xm_out : xu_out)) + local * 16 + lane * 2;
    o4[0] = r0;
    o4[1] = r1;
}

// out[l] = dot(x_u[label_src[l]], x_m[label_dst[l]]); one warp per label.
__global__ void k_labels(const int* __restrict__ ls, const int* __restrict__ ld,
                         int xu_off, int xm_off, float* __restrict__ out, int L) {
    int t = blockIdx.x * blockDim.x + threadIdx.x;
    int l = t >> 5;
    if (l >= L) return;
    int lane = t & 31;
    const float2* xu = (const float2*)(g_buf + xu_off);
    const float2* xm = (const float2*)(g_buf + xm_off);
    int s = __ldg(ls + l), d = __ldg(ld + l);
    float2 a = __ldg(xu + s * 32 + lane);
    float2 b = __ldg(xm + d * 32 + lane);
    float v = fmaf(a.x, b.x, a.y * b.y);
#pragma unroll
    for (int off = 16; off; off >>= 1) v += __shfl_xor_sync(0xffffffffu, v, off);
    if (lane == 0) out[l] = v;
}

// ---------------------------------------------------------------------------
extern "C" void kernel_launch(void* const* d_in, const int* in_sizes, int n_in,
                              void* d_out, int out_size) {
    const float* movie_x   = (const float*)d_in[0];
    const float* user_emb  = (const float*)d_in[1];
    const float* movie_emb = (const float*)d_in[2];
    const float* mw        = (const float*)d_in[3];
    const float* mb        = (const float*)d_in[4];
    const float* wl        = (const float*)d_in[5];
    const float* blb       = (const float*)d_in[6];
    const float* wr        = (const float*)d_in[7];
    const int*   es        = (const int*)d_in[8];
    const int*   ed        = (const int*)d_in[9];
    const int*   ls        = (const int*)d_in[10];
    const int*   ld        = (const int*)d_in[11];
    float* out = (float*)d_out;

    const int U = in_sizes[1] / HH;
    const int M = in_sizes[2] / HH;
    const int E = in_sizes[8];
    const int L = in_sizes[10];
    const int TB = 256;

    // launch 1: zero degree counters
    k_zero_deg<<<(U + M + TB - 1) / TB, TB>>>(U + M);
    // launch 2: fused feature init (movies projected, users copied)
    const int MB4 = (M + 3) / 4;
    const int UBc = (U * 16 + TB - 1) / TB;
    k_init<<<MB4 + UBc, TB>>>((const float4*)user_emb, movie_x, mw, mb, movie_emb,
                              MB4, M, U);
    // launch 3: adjacency buckets (+degree counting)
    k_fill<<<(E + TB - 1) / TB, TB>>>(es, ed, E);

    const int MBLK = (M + PROWS - 1) / PROWS;
    const int UBLK = (U + PROWS - 1) / PROWS;
    const int GAB  = (int)(((long)(M + U) * 8 + TB - 1) / TB);
    for (int layer = 0; layer < 2; layer++) {
        const int xu_in  = layer ? OFF_XU1 : OFF_XU0;
        const int xm_in  = layer ? OFF_XM1 : OFF_XM0;
        const int xu_out = layer ? OFF_XU0 : OFF_XU1;
        const int xm_out = layer ? OFF_XM0 : OFF_XM1;

        // launch 4 (profiled on layer 0): dense pre-transform y,z
        k_pre<<<MBLK + UBLK, 256>>>(xm_in, xu_in, wl, blb, wr, layer, MBLK, M, U);
        // gather-mean(y) + z (+relu)
        k_gather_add<<<GAB, TB>>>(xm_out, xu_out, M, U, layer == 0);
    }

    // final features are in the *0 buffers
    long lt = (long)L * 32;
    k_labels<<<(int)((lt + TB - 1) / TB), TB>>>(ls, ld, OFF_XU0, OFF_XM0, out, L);
}

// round 8
// speedup vs baseline: 1.7077x; 1.0079x over previous
#include <cuda_runtime.h>
#include <cuda_fp16.h>

// Problem constants (shapes fixed by the dataset)
#define UQ 100000          // users
#define MQ 50000           // movies
#define HH 64              // hidden dim
#define UN (UQ*HH)
#define MN (MQ*HH)
#define PAD_U 64           // max user degree slots (Poisson(20) tail safe)
#define PAD_M 128          // max movie degree slots (Poisson(40) tail safe)

// Scratch layout inside one big __device__ buffer (offsets in floats)
#define OFF_XU0  0
#define OFF_XU1  (OFF_XU0 + UN)
#define OFF_XM0  (OFF_XU1 + UN)
#define OFF_XM1  (OFF_XM0 + MN)
#define OFF_ZU   (OFF_XM1 + MN)      // z_u = x_u @ Wr^T + b   [U,64] fp32
#define OFF_ZM   (OFF_ZU + UN)       // z_m = x_m @ Wr^T + b   [M,64] fp32
#define TOTAL_F  (OFF_ZM + MN)

__device__ __align__(16) float g_buf[TOTAL_F];        // ~115 MB scratch
__device__ int g_deg[UQ + MQ];                        // users then movies (fill cursors)
__device__ __align__(16) int g_bucket_u[UQ * PAD_U];  // movie ids per user
__device__ __align__(16) int g_bucket_m[MQ * PAD_M];  // user ids per movie
__device__ __align__(16) __half g_hyu[UN];            // y_u = x_u @ Wl[l,0]^T (fp16)
__device__ __align__(16) __half g_hym[MN];            // y_m = x_m @ Wl[l,1]^T (fp16)

// ---------------------------------------------------------------------------
__global__ void k_zero_deg(int n) {
    int i = blockIdx.x * blockDim.x + threadIdx.x;
    if (i < n) g_deg[i] = 0;
}

// Fused init: movie blocks compute x_m0 = movie_x @ W.T + b + movie_emb
// (4 rows/block, 256 thr); user blocks copy user_emb into g_buf.
__global__ void __launch_bounds__(256)
k_init(const float4* __restrict__ uemb,
       const float* __restrict__ mx, const float* __restrict__ w,
       const float* __restrict__ b, const float* __restrict__ memb,
       int MB4, int M, int U) {
    int tid = threadIdx.x;
    if ((int)blockIdx.x < MB4) {
        __shared__ float xs[4][20];
        int r = tid >> 6, o = tid & 63;
        int row = blockIdx.x * 4 + r;
        if (tid < 80) {
            int rr = tid / 20, cc = tid % 20;
            int g = blockIdx.x * 4 + rr;
            if (g < M) xs[rr][cc] = __ldg(mx + g * 20 + cc);
        }
        __syncthreads();
        if (row < M) {
            float acc = __ldg(b + o) + __ldg(memb + row * 64 + o);
#pragma unroll
            for (int k = 0; k < 20; k++) acc = fmaf(xs[r][k], __ldg(w + o * 20 + k), acc);
            g_buf[OFF_XM0 + row * 64 + o] = acc;
        }
    } else {
        int i = ((int)blockIdx.x - MB4) * 256 + tid;
        if (i < U * 16) ((float4*)(g_buf + OFF_XU0))[i] = __ldg(uemb + i);
    }
}

// Bucket fill: degree counting and slot allocation in one pass over edges.
__global__ void k_fill(const int* __restrict__ es, const int* __restrict__ ed, int E) {
    int e = blockIdx.x * blockDim.x + threadIdx.x;
    if (e >= E) return;
    int u = __ldg(es + e), m = __ldg(ed + e);
    int su = atomicAdd(&g_deg[u], 1);
    if (su < PAD_U) g_bucket_u[u * PAD_U + su] = m;
    int sm = atomicAdd(&g_deg[UQ + m], 1);
    if (sm < PAD_M) g_bucket_m[m * PAD_M + sm] = u;
}

// ---------------------------------------------------------------------------
// Pre-transform (dense, per node): y = x @ Wl_y^T (fp16, feeds the gather),
// z = x @ Wr_z^T + b (fp32, dst-side term).
// 256 threads, 32 rows/block; thread = 2 rows x (4 y-outs + 4 z-outs).
// Per inner i: 2 LDS.128 (weights) + 2 broadcast LDS.32 (x) for 16 FMA.
#define PROWS 32
#define WPAD 68            // 68*4 B = 272 = 17*16 -> float4-aligned, rows 4 banks apart
__global__ void __launch_bounds__(256)
k_pre(int xm_off, int xu_off, const float* __restrict__ wl,
      const float* __restrict__ bl, const float* __restrict__ wr,
      int layer, int MBLK, int M, int U) {
    __shared__ float wsy[64 * WPAD];      // Wl_y transposed [i][o]
    __shared__ float wsz[64 * WPAD];      // Wr_z transposed [i][o]
    __shared__ float rs[PROWS * WPAD];    // x rows
    const bool is_movie = (int)blockIdx.x < MBLK;
    // movies: y feeds user-dst edges (et=1); z is dst term of movie-dst edges (et=0)
    const int et_y = is_movie ? 1 : 0;
    const int et_z = is_movie ? 0 : 1;
    const float* wly = wl + (layer * 2 + et_y) * 4096;
    const float* wrz = wr + (layer * 2 + et_z) * 4096;
    const float* blz = bl + (layer * 2 + et_z) * 64;
    const int nrows = is_movie ? M : U;
    const int x_off = is_movie ? xm_off : xu_off;
    const int z_off = is_movie ? OFF_ZM : OFF_ZU;
    __half* ytab    = is_movie ? g_hym : g_hyu;
    const int row0  = (is_movie ? blockIdx.x : blockIdx.x - MBLK) * PROWS;
    int tid = threadIdx.x;

    for (int idx = tid; idx < 4096; idx += 256) {
        int o = idx >> 6, i = idx & 63;   // idx = o*64+i (coalesced global read)
        wsy[i * WPAD + o] = __ldg(wly + idx);
        wsz[i * WPAD + o] = __ldg(wrz + idx);
    }
    const float4* x4 = (const float4*)(g_buf + x_off);
    {
        int r = tid >> 4, q = tid & 15;   // 256 threads = 32 rows x 8... -> 16 rows/pass
#pragma unroll
        for (int rr = r; rr < PROWS; rr += 16) {
            int g = row0 + rr;
            if (g < nrows) *(float4*)&rs[rr * WPAD + q * 4] = __ldg(x4 + g * 16 + q);
        }
    }
    __syncthreads();

    int og = tid & 15, rg = tid >> 4;     // 16 o-groups x 16 row-groups
    int o0 = og * 4, r0 = rg * 2;
    float4 bz = *(const float4*)(blz + o0);
    float y0x = 0.f, y0y = 0.f, y0z = 0.f, y0w = 0.f;
    float y1x = 0.f, y1y = 0.f, y1z = 0.f, y1w = 0.f;
    float z0x = bz.x, z0y = bz.y, z0z = bz.z, z0w = bz.w;
    float z1x = bz.x, z1y = bz.y, z1z = bz.z, z1w = bz.w;

#pragma unroll 8
    for (int i = 0; i < 64; i++) {
        float4 wy = *(const float4*)&wsy[i * WPAD + o0];
        float4 wz = *(const float4*)&wsz[i * WPAD + o0];
        float x0 = rs[r0 * WPAD + i];
        float x1 = rs[(r0 + 1) * WPAD + i];
        y0x = fmaf(x0, wy.x, y0x); y0y = fmaf(x0, wy.y, y0y);
        y0z = fmaf(x0, wy.z, y0z); y0w = fmaf(x0, wy.w, y0w);
        z0x = fmaf(x0, wz.x, z0x); z0y = fmaf(x0, wz.y, z0y);
        z0z = fmaf(x0, wz.z, z0z); z0w = fmaf(x0, wz.w, z0w);
        y1x = fmaf(x1, wy.x, y1x); y1y = fmaf(x1, wy.y, y1y);
        y1z = fmaf(x1, wy.z, y1z); y1w = fmaf(x1, wy.w, y1w);
        z1x = fmaf(x1, wz.x, z1x); z1y = fmaf(x1, wz.y, z1y);
        z1z = fmaf(x1, wz.z, z1z); z1w = fmaf(x1, wz.w, z1w);
    }
    float* z = g_buf + z_off;
    int g0 = row0 + r0;
    if (g0 < nrows) {
        *(float4*)(z + g0 * 64 + o0) = make_float4(z0x, z0y, z0z, z0w);
        uint2 p;
        ((__half2*)&p)[0] = __floats2half2_rn(y0x, y0y);
        ((__half2*)&p)[1] = __floats2half2_rn(y0z, y0w);
        *(uint2*)(ytab + g0 * 64 + o0) = p;
    }
    if (g0 + 1 < nrows) {
        *(float4*)(z + (g0 + 1) * 64 + o0) = make_float4(z1x, z1y, z1z, z1w);
        uint2 p;
        ((__half2*)&p)[0] = __floats2half2_rn(y1x, y1y);
        ((__half2*)&p)[1] = __floats2half2_rn(y1z, y1w);
        *(uint2*)(ytab + (g0 + 1) * 64 + o0) = p;
    }
}

// ---------------------------------------------------------------------------
__device__ __forceinline__ void acc8(float* a, uint4 v) {
    float2 f;
    f = __half22float2(*(__half2*)&v.x); a[0] += f.x; a[1] += f.y;
    f = __half22float2(*(__half2*)&v.y); a[2] += f.x; a[3] += f.y;
    f = __half22float2(*(__half2*)&v.z); a[4] += f.x; a[5] += f.y;
    f = __half22float2(*(__half2*)&v.w); a[6] += f.x; a[7] += f.y;
}

// Gather-mean of fp16 y rows + z + optional relu -> x_new (fp32).
// 8 lanes per node (y row = 128 B = one cache line), unroll 8 (MLP=8).
__global__ void k_gather_add(int xm_out, int xu_out, int M, int U, int do_relu) {
    int t = blockIdx.x * blockDim.x + threadIdx.x;
    int node = t >> 3;
    if (node >= M + U) return;
    int lane = t & 7;
    bool is_movie = node < M;
    int local = is_movie ? node : node - M;
    const int pad = is_movie ? PAD_M : PAD_U;
    const int* bk = (is_movie ? g_bucket_m : g_bucket_u) + (long)local * pad;
    int dt = g_deg[(is_movie ? UQ : 0) + local];
    float iv = 1.f / fmaxf((float)dt, 1.f);
    int d = min(dt, pad);
    const uint4* y4 = (const uint4*)(is_movie ? g_hyu : g_hym);  // gather OTHER side's y

    float a[8]  = {0.f, 0.f, 0.f, 0.f, 0.f, 0.f, 0.f, 0.f};
    float a2[8] = {0.f, 0.f, 0.f, 0.f, 0.f, 0.f, 0.f, 0.f};
    int i = 0;
    for (; i + 8 <= d; i += 8) {
        int4 na = __ldg((const int4*)(bk + i));
        int4 nb = __ldg((const int4*)(bk + i + 4));
        uint4 v0 = __ldg(y4 + na.x * 8 + lane);
        uint4 v1 = __ldg(y4 + na.y * 8 + lane);
        uint4 v2 = __ldg(y4 + na.z * 8 + lane);
        uint4 v3 = __ldg(y4 + na.w * 8 + lane);
        uint4 v4 = __ldg(y4 + nb.x * 8 + lane);
        uint4 v5 = __ldg(y4 + nb.y * 8 + lane);
        uint4 v6 = __ldg(y4 + nb.z * 8 + lane);
        uint4 v7 = __ldg(y4 + nb.w * 8 + lane);
        acc8(a, v0); acc8(a, v1); acc8(a, v2); acc8(a, v3);
        acc8(a2, v4); acc8(a2, v5); acc8(a2, v6); acc8(a2, v7);
    }
    for (; i + 4 <= d; i += 4) {
        int4 na = __ldg((const int4*)(bk + i));
        uint4 v0 = __ldg(y4 + na.x * 8 + lane);
        uint4 v1 = __ldg(y4 + na.y * 8 + lane);
        uint4 v2 = __ldg(y4 + na.z * 8 + lane);
        uint4 v3 = __ldg(y4 + na.w * 8 + lane);
        acc8(a, v0); acc8(a, v1); acc8(a, v2); acc8(a, v3);
    }
    for (; i < d; i++) {
        int nb = __ldg(bk + i);
        acc8(a, __ldg(y4 + nb * 8 + lane));
    }
#pragma unroll
    for (int k = 0; k < 8; k++) a[k] += a2[k];
    const float4* zp = (const float4*)(g_buf + (is_movie ? OFF_ZM : OFF_ZU)) + local * 16 + lane * 2;
    float4 z0 = __ldg(zp), z1 = __ldg(zp + 1);
    float4 r0 = make_float4(fmaf(a[0], iv, z0.x), fmaf(a[1], iv, z0.y),
                            fmaf(a[2], iv, z0.z), fmaf(a[3], iv, z0.w));
    float4 r1 = make_float4(fmaf(a[4], iv, z1.x), fmaf(a[5], iv, z1.y),
                            fmaf(a[6], iv, z1.z), fmaf(a[7], iv, z1.w));
    if (do_relu) {
        r0.x = fmaxf(r0.x, 0.f); r0.y = fmaxf(r0.y, 0.f);
        r0.z = fmaxf(r0.z, 0.f); r0.w = fmaxf(r0.w, 0.f);
        r1.x = fmaxf(r1.x, 0.f); r1.y = fmaxf(r1.y, 0.f);
        r1.z = fmaxf(r1.z, 0.f); r1.w = fmaxf(r1.w, 0.f);
    }
    float4* o4 = (float4*)(g_buf + (is_movie ? xm_out : xu_out)) + local * 16 + lane * 2;
    o4[0] = r0;
    o4[1] = r1;
}

// out[l] = dot(x_u[label_src[l]], x_m[label_dst[l]]); one warp per label.
__global__ void k_labels(const int* __restrict__ ls, const int* __restrict__ ld,
                         int xu_off, int xm_off, float* __restrict__ out, int L) {
    int t = blockIdx.x * blockDim.x + threadIdx.x;
    int l = t >> 5;
    if (l >= L) return;
    int lane = t & 31;
    const float2* xu = (const float2*)(g_buf + xu_off);
    const float2* xm = (const float2*)(g_buf + xm_off);
    int s = __ldg(ls + l), d = __ldg(ld + l);
    float2 a = __ldg(xu + s * 32 + lane);
    float2 b = __ldg(xm + d * 32 + lane);
    float v = fmaf(a.x, b.x, a.y * b.y);
#pragma unroll
    for (int off = 16; off; off >>= 1) v += __shfl_xor_sync(0xffffffffu, v, off);
    if (lane == 0) out[l] = v;
}

// ---------------------------------------------------------------------------
extern "C" void kernel_launch(void* const* d_in, const int* in_sizes, int n_in,
                              void* d_out, int out_size) {
    const float* movie_x   = (const float*)d_in[0];
    const float* user_emb  = (const float*)d_in[1];
    const float* movie_emb = (const float*)d_in[2];
    const float* mw        = (const float*)d_in[3];
    const float* mb        = (const float*)d_in[4];
    const float* wl        = (const float*)d_in[5];
    const float* blb       = (const float*)d_in[6];
    const float* wr        = (const float*)d_in[7];
    const int*   es        = (const int*)d_in[8];
    const int*   ed        = (const int*)d_in[9];
    const int*   ls        = (const int*)d_in[10];
    const int*   ld        = (const int*)d_in[11];
    float* out = (float*)d_out;

    const int U = in_sizes[1] / HH;
    const int M = in_sizes[2] / HH;
    const int E = in_sizes[8];
    const int L = in_sizes[10];
    const int TB = 256;

    // launch 1: zero degree counters
    k_zero_deg<<<(U + M + TB - 1) / TB, TB>>>(U + M);
    // launch 2: fused feature init (movies projected, users copied)
    const int MB4 = (M + 3) / 4;
    const int UBc = (U * 16 + TB - 1) / TB;
    k_init<<<MB4 + UBc, TB>>>((const float4*)user_emb, movie_x, mw, mb, movie_emb,
                              MB4, M, U);
    // launch 3: adjacency buckets (+degree counting)
    k_fill<<<(E + TB - 1) / TB, TB>>>(es, ed, E);

    const int MBLK = (M + PROWS - 1) / PROWS;
    const int UBLK = (U + PROWS - 1) / PROWS;
    const int GAB  = (int)(((long)(M + U) * 8 + TB - 1) / TB);
    for (int layer = 0; layer < 2; layer++) {
        const int xu_in  = layer ? OFF_XU1 : OFF_XU0;
        const int xm_in  = layer ? OFF_XM1 : OFF_XM0;
        const int xu_out = layer ? OFF_XU0 : OFF_XU1;
        const int xm_out = layer ? OFF_XM0 : OFF_XM1;

        // launch 4 (profiled on layer 0): dense pre-transform y,z
        k_pre<<<MBLK + UBLK, 256>>>(xm_in, xu_in, wl, blb, wr, layer, MBLK, M, U);
        // gather-mean(y) + z (+relu)
        k_gather_add<<<GAB, TB>>>(xm_out, xu_out, M, U, layer == 0);
    }

    // final features are in the *0 buffers
    long lt = (long)L * 32;
    k_labels<<<(int)((lt + TB - 1) / TB), TB>>>(ls, ld, OFF_XU0, OFF_XM0, out, L);
}

// round 9
// speedup vs baseline: 1.7303x; 1.0132x over previous
#include <cuda_runtime.h>
#include <cuda_fp16.h>

// Problem constants (shapes fixed by the dataset)
#define UQ 100000          // users
#define MQ 50000           // movies
#define HH 64              // hidden dim
#define UN (UQ*HH)
#define MN (MQ*HH)
#define PAD_U 64           // max user degree slots (Poisson(20) tail safe)
#define PAD_M 128          // max movie degree slots (Poisson(40) tail safe)

// Scratch layout inside one big __device__ buffer (offsets in floats)
#define OFF_XU0  0
#define OFF_XU1  (OFF_XU0 + UN)
#define OFF_XM0  (OFF_XU1 + UN)
#define OFF_XM1  (OFF_XM0 + MN)
#define OFF_ZU   (OFF_XM1 + MN)      // z_u = x_u @ Wr^T + b   [U,64] fp32
#define OFF_ZM   (OFF_ZU + UN)       // z_m = x_m @ Wr^T + b   [M,64] fp32
#define TOTAL_F  (OFF_ZM + MN)

__device__ __align__(16) float g_buf[TOTAL_F];        // ~115 MB scratch
__device__ int g_deg[UQ + MQ];                        // users then movies (fill cursors)
__device__ __align__(16) int g_bucket_u[UQ * PAD_U];  // movie ids per user
__device__ __align__(16) int g_bucket_m[MQ * PAD_M];  // user ids per movie
__device__ __align__(16) __half g_hyu[UN];            // y_u = x_u @ Wl[l,0]^T (fp16)
__device__ __align__(16) __half g_hym[MN];            // y_m = x_m @ Wl[l,1]^T (fp16)

// ---------------------------------------------------------------------------
// Packed f32x2 helpers (Blackwell sm_103a FFMA2 path)
__device__ __forceinline__ unsigned long long pack_dup(float x) {
    unsigned long long r;
    asm("mov.b64 %0, {%1, %1};" : "=l"(r) : "f"(x));
    return r;
}
__device__ __forceinline__ unsigned long long pack2(float a, float b) {
    unsigned long long r;
    asm("mov.b64 %0, {%1, %2};" : "=l"(r) : "f"(a), "f"(b));
    return r;
}
__device__ __forceinline__ void ffma2(unsigned long long& d,
                                      unsigned long long a, unsigned long long b) {
    asm("fma.rn.f32x2 %0, %1, %2, %0;" : "+l"(d) : "l"(a), "l"(b));
}
__device__ __forceinline__ float2 unpack2(unsigned long long v) {
    float2 f;
    asm("mov.b64 {%0, %1}, %2;" : "=f"(f.x), "=f"(f.y) : "l"(v));
    return f;
}

// ---------------------------------------------------------------------------
__global__ void k_zero_deg(int n) {
    int i = blockIdx.x * blockDim.x + threadIdx.x;
    if (i < n) g_deg[i] = 0;
}

// Fused init: movie blocks compute x_m0 = movie_x @ W.T + b + movie_emb
// (4 rows/block, 256 thr); user blocks copy user_emb into g_buf.
__global__ void __launch_bounds__(256)
k_init(const float4* __restrict__ uemb,
       const float* __restrict__ mx, const float* __restrict__ w,
       const float* __restrict__ b, const float* __restrict__ memb,
       int MB4, int M, int U) {
    int tid = threadIdx.x;
    if ((int)blockIdx.x < MB4) {
        __shared__ float xs[4][20];
        int r = tid >> 6, o = tid & 63;
        int row = blockIdx.x * 4 + r;
        if (tid < 80) {
            int rr = tid / 20, cc = tid % 20;
            int g = blockIdx.x * 4 + rr;
            if (g < M) xs[rr][cc] = __ldg(mx + g * 20 + cc);
        }
        __syncthreads();
        if (row < M) {
            float acc = __ldg(b + o) + __ldg(memb + row * 64 + o);
#pragma unroll
            for (int k = 0; k < 20; k++) acc = fmaf(xs[r][k], __ldg(w + o * 20 + k), acc);
            g_buf[OFF_XM0 + row * 64 + o] = acc;
        }
    } else {
        int i = ((int)blockIdx.x - MB4) * 256 + tid;
        if (i < U * 16) ((float4*)(g_buf + OFF_XU0))[i] = __ldg(uemb + i);
    }
}

// Bucket fill: degree counting and slot allocation in one pass over edges.
__global__ void k_fill(const int* __restrict__ es, const int* __restrict__ ed, int E) {
    int e = blockIdx.x * blockDim.x + threadIdx.x;
    if (e >= E) return;
    int u = __ldg(es + e), m = __ldg(ed + e);
    int su = atomicAdd(&g_deg[u], 1);
    if (su < PAD_U) g_bucket_u[u * PAD_U + su] = m;
    int sm = atomicAdd(&g_deg[UQ + m], 1);
    if (sm < PAD_M) g_bucket_m[m * PAD_M + sm] = u;
}

// ---------------------------------------------------------------------------
// Pre-transform (dense, per node): y = x @ Wl_y^T (fp16, feeds the gather),
// z = x @ Wr_z^T + b (fp32, dst-side term).
// 256 threads, 32 rows/block; thread = 2 rows x (4 y-outs + 4 z-outs).
// Inner i: 2 LDS.128 (weights as ulonglong2) + 2 bcast LDS.32 + 2 packs + 8 FFMA2.
#define PROWS 32
#define WPAD 68            // 68*4 B = 272 = 17*16 -> float4-aligned, rows 4 banks apart
__global__ void __launch_bounds__(256)
k_pre(int xm_off, int xu_off, const float* __restrict__ wl,
      const float* __restrict__ bl, const float* __restrict__ wr,
      int layer, int MBLK, int M, int U) {
    __shared__ float wsy[64 * WPAD];      // Wl_y transposed [i][o]
    __shared__ float wsz[64 * WPAD];      // Wr_z transposed [i][o]
    __shared__ float rs[PROWS * WPAD];    // x rows
    const bool is_movie = (int)blockIdx.x < MBLK;
    // movies: y feeds user-dst edges (et=1); z is dst term of movie-dst edges (et=0)
    const int et_y = is_movie ? 1 : 0;
    const int et_z = is_movie ? 0 : 1;
    const float* wly = wl + (layer * 2 + et_y) * 4096;
    const float* wrz = wr + (layer * 2 + et_z) * 4096;
    const float* blz = bl + (layer * 2 + et_z) * 64;
    const int nrows = is_movie ? M : U;
    const int x_off = is_movie ? xm_off : xu_off;
    const int z_off = is_movie ? OFF_ZM : OFF_ZU;
    __half* ytab    = is_movie ? g_hym : g_hyu;
    const int row0  = (is_movie ? blockIdx.x : blockIdx.x - MBLK) * PROWS;
    int tid = threadIdx.x;

    for (int idx = tid; idx < 4096; idx += 256) {
        int o = idx >> 6, i = idx & 63;   // idx = o*64+i (coalesced global read)
        wsy[i * WPAD + o] = __ldg(wly + idx);
        wsz[i * WPAD + o] = __ldg(wrz + idx);
    }
    const float4* x4 = (const float4*)(g_buf + x_off);
    {
        int r = tid >> 4, q = tid & 15;
#pragma unroll
        for (int rr = r; rr < PROWS; rr += 16) {
            int g = row0 + rr;
            if (g < nrows) *(float4*)&rs[rr * WPAD + q * 4] = __ldg(x4 + g * 16 + q);
        }
    }
    __syncthreads();

    int og = tid & 15, rg = tid >> 4;     // 16 o-groups x 16 row-groups
    int o0 = og * 4, r0 = rg * 2;
    float4 bz = *(const float4*)(blz + o0);
    unsigned long long y0a = 0ull, y0b = 0ull, y1a = 0ull, y1b = 0ull;
    unsigned long long z0a = pack2(bz.x, bz.y), z0b = pack2(bz.z, bz.w);
    unsigned long long z1a = z0a, z1b = z0b;

#pragma unroll 16
    for (int i = 0; i < 64; i++) {
        ulonglong2 wy = *(const ulonglong2*)&wsy[i * WPAD + o0];
        ulonglong2 wz = *(const ulonglong2*)&wsz[i * WPAD + o0];
        unsigned long long px0 = pack_dup(rs[r0 * WPAD + i]);
        unsigned long long px1 = pack_dup(rs[(r0 + 1) * WPAD + i]);
        ffma2(y0a, px0, wy.x); ffma2(y0b, px0, wy.y);
        ffma2(z0a, px0, wz.x); ffma2(z0b, px0, wz.y);
        ffma2(y1a, px1, wy.x); ffma2(y1b, px1, wy.y);
        ffma2(z1a, px1, wz.x); ffma2(z1b, px1, wz.y);
    }
    float2 y0xy = unpack2(y0a), y0zw = unpack2(y0b);
    float2 y1xy = unpack2(y1a), y1zw = unpack2(y1b);
    float2 z0xy = unpack2(z0a), z0zw = unpack2(z0b);
    float2 z1xy = unpack2(z1a), z1zw = unpack2(z1b);

    float* z = g_buf + z_off;
    int g0 = row0 + r0;
    if (g0 < nrows) {
        *(float4*)(z + g0 * 64 + o0) = make_float4(z0xy.x, z0xy.y, z0zw.x, z0zw.y);
        uint2 p;
        ((__half2*)&p)[0] = __floats2half2_rn(y0xy.x, y0xy.y);
        ((__half2*)&p)[1] = __floats2half2_rn(y0zw.x, y0zw.y);
        *(uint2*)(ytab + g0 * 64 + o0) = p;
    }
    if (g0 + 1 < nrows) {
        *(float4*)(z + (g0 + 1) * 64 + o0) = make_float4(z1xy.x, z1xy.y, z1zw.x, z1zw.y);
        uint2 p;
        ((__half2*)&p)[0] = __floats2half2_rn(y1xy.x, y1xy.y);
        ((__half2*)&p)[1] = __floats2half2_rn(y1zw.x, y1zw.y);
        *(uint2*)(ytab + (g0 + 1) * 64 + o0) = p;
    }
}

// ---------------------------------------------------------------------------
__device__ __forceinline__ void acc8(float* a, uint4 v) {
    float2 f;
    f = __half22float2(*(__half2*)&v.x); a[0] += f.x; a[1] += f.y;
    f = __half22float2(*(__half2*)&v.y); a[2] += f.x; a[3] += f.y;
    f = __half22float2(*(__half2*)&v.z); a[4] += f.x; a[5] += f.y;
    f = __half22float2(*(__half2*)&v.w); a[6] += f.x; a[7] += f.y;
}

// Gather-mean of fp16 y rows + z + optional relu -> x_new (fp32).
// 8 lanes per node (y row = 128 B = one cache line), unroll 8 (MLP=8).
__global__ void k_gather_add(int xm_out, int xu_out, int M, int U, int do_relu) {
    int t = blockIdx.x * blockDim.x + threadIdx.x;
    int node = t >> 3;
    if (node >= M + U) return;
    int lane = t & 7;
    bool is_movie = node < M;
    int local = is_movie ? node : node - M;
    const int pad = is_movie ? PAD_M : PAD_U;
    const int* bk = (is_movie ? g_bucket_m : g_bucket_u) + (long)local * pad;
    int dt = g_deg[(is_movie ? UQ : 0) + local];
    float iv = 1.f / fmaxf((float)dt, 1.f);
    int d = min(dt, pad);
    const uint4* y4 = (const uint4*)(is_movie ? g_hyu : g_hym);  // gather OTHER side's y

    float a[8]  = {0.f, 0.f, 0.f, 0.f, 0.f, 0.f, 0.f, 0.f};
    float a2[8] = {0.f, 0.f, 0.f, 0.f, 0.f, 0.f, 0.f, 0.f};
    int i = 0;
    for (; i + 8 <= d; i += 8) {
        int4 na = __ldg((const int4*)(bk + i));
        int4 nb = __ldg((const int4*)(bk + i + 4));
        uint4 v0 = __ldg(y4 + na.x * 8 + lane);
        uint4 v1 = __ldg(y4 + na.y * 8 + lane);
        uint4 v2 = __ldg(y4 + na.z * 8 + lane);
        uint4 v3 = __ldg(y4 + na.w * 8 + lane);
        uint4 v4 = __ldg(y4 + nb.x * 8 + lane);
        uint4 v5 = __ldg(y4 + nb.y * 8 + lane);
        uint4 v6 = __ldg(y4 + nb.z * 8 + lane);
        uint4 v7 = __ldg(y4 + nb.w * 8 + lane);
        acc8(a, v0); acc8(a, v1); acc8(a, v2); acc8(a, v3);
        acc8(a2, v4); acc8(a2, v5); acc8(a2, v6); acc8(a2, v7);
    }
    for (; i + 4 <= d; i += 4) {
        int4 na = __ldg((const int4*)(bk + i));
        uint4 v0 = __ldg(y4 + na.x * 8 + lane);
        uint4 v1 = __ldg(y4 + na.y * 8 + lane);
        uint4 v2 = __ldg(y4 + na.z * 8 + lane);
        uint4 v3 = __ldg(y4 + na.w * 8 + lane);
        acc8(a, v0); acc8(a, v1); acc8(a, v2); acc8(a, v3);
    }
    for (; i < d; i++) {
        int nb = __ldg(bk + i);
        acc8(a, __ldg(y4 + nb * 8 + lane));
    }
#pragma unroll
    for (int k = 0; k < 8; k++) a[k] += a2[k];
    const float4* zp = (const float4*)(g_buf + (is_movie ? OFF_ZM : OFF_ZU)) + local * 16 + lane * 2;
    float4 z0 = __ldg(zp), z1 = __ldg(zp + 1);
    float4 r0 = make_float4(fmaf(a[0], iv, z0.x), fmaf(a[1], iv, z0.y),
                            fmaf(a[2], iv, z0.z), fmaf(a[3], iv, z0.w));
    float4 r1 = make_float4(fmaf(a[4], iv, z1.x), fmaf(a[5], iv, z1.y),
                            fmaf(a[6], iv, z1.z), fmaf(a[7], iv, z1.w));
    if (do_relu) {
        r0.x = fmaxf(r0.x, 0.f); r0.y = fmaxf(r0.y, 0.f);
        r0.z = fmaxf(r0.z, 0.f); r0.w = fmaxf(r0.w, 0.f);
        r1.x = fmaxf(r1.x, 0.f); r1.y = fmaxf(r1.y, 0.f);
        r1.z = fmaxf(r1.z, 0.f); r1.w = fmaxf(r1.w, 0.f);
    }
    float4* o4 = (float4*)(g_buf + (is_movie ? xm_out : xu_out)) + local * 16 + lane * 2;
    o4[0] = r0;
    o4[1] = r1;
}

// out[l] = dot(x_u[label_src[l]], x_m[label_dst[l]]); one warp per label.
__global__ void k_labels(const int* __restrict__ ls, const int* __restrict__ ld,
                         int xu_off, int xm_off, float* __restrict__ out, int L) {
    int t = blockIdx.x * blockDim.x + threadIdx.x;
    int l = t >> 5;
    if (l >= L) return;
    int lane = t & 31;
    const float2* xu = (const float2*)(g_buf + xu_off);
    const float2* xm = (const float2*)(g_buf + xm_off);
    int s = __ldg(ls + l), d = __ldg(ld + l);
    float2 a = __ldg(xu + s * 32 + lane);
    float2 b = __ldg(xm + d * 32 + lane);
    float v = fmaf(a.x, b.x, a.y * b.y);
#pragma unroll
    for (int off = 16; off; off >>= 1) v += __shfl_xor_sync(0xffffffffu, v, off);
    if (lane == 0) out[l] = v;
}

// ---------------------------------------------------------------------------
extern "C" void kernel_launch(void* const* d_in, const int* in_sizes, int n_in,
                              void* d_out, int out_size) {
    const float* movie_x   = (const float*)d_in[0];
    const float* user_emb  = (const float*)d_in[1];
    const float* movie_emb = (const float*)d_in[2];
    const float* mw        = (const float*)d_in[3];
    const float* mb        = (const float*)d_in[4];
    const float* wl        = (const float*)d_in[5];
    const float* blb       = (const float*)d_in[6];
    const float* wr        = (const float*)d_in[7];
    const int*   es        = (const int*)d_in[8];
    const int*   ed        = (const int*)d_in[9];
    const int*   ls        = (const int*)d_in[10];
    const int*   ld        = (const int*)d_in[11];
    float* out = (float*)d_out;

    const int U = in_sizes[1] / HH;
    const int M = in_sizes[2] / HH;
    const int E = in_sizes[8];
    const int L = in_sizes[10];
    const int TB = 256;

    // launch 1: zero degree counters
    k_zero_deg<<<(U + M + TB - 1) / TB, TB>>>(U + M);
    // launch 2: fused feature init (movies projected, users copied)
    const int MB4 = (M + 3) / 4;
    const int UBc = (U * 16 + TB - 1) / TB;
    k_init<<<MB4 + UBc, TB>>>((const float4*)user_emb, movie_x, mw, mb, movie_emb,
                              MB4, M, U);
    // launch 3: adjacency buckets (+degree counting)
    k_fill<<<(E + TB - 1) / TB, TB>>>(es, ed, E);

    const int MBLK = (M + PROWS - 1) / PROWS;
    const int UBLK = (U + PROWS - 1) / PROWS;
    const int GAB  = (int)(((long)(M + U) * 8 + TB - 1) / TB);
    for (int layer = 0; layer < 2; layer++) {
        const int xu_in  = layer ? OFF_XU1 : OFF_XU0;
        const int xm_in  = layer ? OFF_XM1 : OFF_XM0;
        const int xu_out = layer ? OFF_XU0 : OFF_XU1;
        const int xm_out = layer ? OFF_XM0 : OFF_XM1;

        // launch 4 (profiled on layer 0): dense pre-transform y,z
        k_pre<<<MBLK + UBLK, 256>>>(xm_in, xu_in, wl, blb, wr, layer, MBLK, M, U);
        // gather-mean(y) + z (+relu)
        k_gather_add<<<GAB, TB>>>(xm_out, xu_out, M, U, layer == 0);
    }

    // final features are in the *0 buffers
    long lt = (long)L * 32;
    k_labels<<<(int)((lt + TB - 1) / TB), TB>>>(ls, ld, OFF_XU0, OFF_XM0, out, L);
}

// round 10
// speedup vs baseline: 1.8250x; 1.0548x over previous
#include <cuda_runtime.h>
#include <cuda_fp16.h>

// Problem constants (shapes fixed by the dataset)
#define UQ 100000          // users
#define MQ 50000           // movies
#define HH 64              // hidden dim
#define UN (UQ*HH)
#define MN (MQ*HH)
#define PAD_U 64           // max user degree slots (Poisson(20) tail safe)
#define PAD_M 128          // max movie degree slots (Poisson(40) tail safe)

// Scratch layout inside one big __device__ buffer (offsets in floats)
#define OFF_XU0  0
#define OFF_XU1  (OFF_XU0 + UN)
#define OFF_XM0  (OFF_XU1 + UN)
#define OFF_XM1  (OFF_XM0 + MN)
#define OFF_ZU   (OFF_XM1 + MN)      // z_u = x_u @ Wr^T + b   [U,64] fp32
#define OFF_ZM   (OFF_ZU + UN)       // z_m = x_m @ Wr^T + b   [M,64] fp32
#define TOTAL_F  (OFF_ZM + MN)

__device__ __align__(16) float g_buf[TOTAL_F];        // ~115 MB scratch
__device__ int g_deg[UQ + MQ];                        // users then movies (fill cursors)
__device__ __align__(16) int g_bucket_u[UQ * PAD_U];  // movie ids per user
__device__ __align__(16) int g_bucket_m[MQ * PAD_M];  // user ids per movie
__device__ __align__(16) __half g_hyu[UN];            // y_u = x_u @ Wl[l,0]^T (fp16)
__device__ __align__(16) __half g_hym[MN];            // y_m = x_m @ Wl[l,1]^T (fp16)

// ---------------------------------------------------------------------------
// Packed f32x2 helpers (Blackwell sm_103a FFMA2 path)
__device__ __forceinline__ unsigned long long pack_dup(float x) {
    unsigned long long r;
    asm("mov.b64 %0, {%1, %1};" : "=l"(r) : "f"(x));
    return r;
}
__device__ __forceinline__ unsigned long long pack2(float a, float b) {
    unsigned long long r;
    asm("mov.b64 %0, {%1, %2};" : "=l"(r) : "f"(a), "f"(b));
    return r;
}
__device__ __forceinline__ void ffma2(unsigned long long& d,
                                      unsigned long long a, unsigned long long b) {
    asm("fma.rn.f32x2 %0, %1, %2, %0;" : "+l"(d) : "l"(a), "l"(b));
}
__device__ __forceinline__ float2 unpack2(unsigned long long v) {
    float2 f;
    asm("mov.b64 {%0, %1}, %2;" : "=f"(f.x), "=f"(f.y) : "l"(v));
    return f;
}

// ---------------------------------------------------------------------------
__global__ void k_zero_deg(int n) {
    int i = blockIdx.x * blockDim.x + threadIdx.x;
    if (i < n) g_deg[i] = 0;
}

// Fused init: movie blocks compute x_m0 = movie_x @ W.T + b + movie_emb
// (4 rows/block, 256 thr); user blocks copy user_emb into g_buf.
__global__ void __launch_bounds__(256)
k_init(const float4* __restrict__ uemb,
       const float* __restrict__ mx, const float* __restrict__ w,
       const float* __restrict__ b, const float* __restrict__ memb,
       int MB4, int M, int U) {
    int tid = threadIdx.x;
    if ((int)blockIdx.x < MB4) {
        __shared__ float xs[4][20];
        int r = tid >> 6, o = tid & 63;
        int row = blockIdx.x * 4 + r;
        if (tid < 80) {
            int rr = tid / 20, cc = tid % 20;
            int g = blockIdx.x * 4 + rr;
            if (g < M) xs[rr][cc] = __ldg(mx + g * 20 + cc);
        }
        __syncthreads();
        if (row < M) {
            float acc = __ldg(b + o) + __ldg(memb + row * 64 + o);
#pragma unroll
            for (int k = 0; k < 20; k++) acc = fmaf(xs[r][k], __ldg(w + o * 20 + k), acc);
            g_buf[OFF_XM0 + row * 64 + o] = acc;
        }
    } else {
        int i = ((int)blockIdx.x - MB4) * 256 + tid;
        if (i < U * 16) ((float4*)(g_buf + OFF_XU0))[i] = __ldg(uemb + i);
    }
}

// Bucket fill: degree counting and slot allocation in one pass over edges.
__global__ void k_fill(const int* __restrict__ es, const int* __restrict__ ed, int E) {
    int e = blockIdx.x * blockDim.x + threadIdx.x;
    if (e >= E) return;
    int u = __ldg(es + e), m = __ldg(ed + e);
    int su = atomicAdd(&g_deg[u], 1);
    if (su < PAD_U) g_bucket_u[u * PAD_U + su] = m;
    int sm = atomicAdd(&g_deg[UQ + m], 1);
    if (sm < PAD_M) g_bucket_m[m * PAD_M + sm] = u;
}

// ---------------------------------------------------------------------------
// Pre-transform (dense, per node): y = x @ Wl_y^T (fp16, feeds the gather),
// z = x @ Wr_z^T + b (fp32, dst-side term).
// PERSISTENT TILES: few blocks, each loads its weights ONCE into smem, then
// grid-strides over 32-row tiles. Thread = 2 rows x (4 y + 4 z) via FFMA2.
#define PROWS 32
#define WPAD 68            // 68*4 B = 272 = 17*16 -> float4-aligned
#define GM_BLOCKS 148      // movie-segment blocks (1 per SM)
#define GU_BLOCKS 296      // user-segment blocks (2 per SM)
__global__ void __launch_bounds__(256)
k_pre(int xm_off, int xu_off, const float* __restrict__ wl,
      const float* __restrict__ bl, const float* __restrict__ wr,
      int layer, int M, int U) {
    __shared__ float wsy[64 * WPAD];      // Wl_y transposed [i][o]
    __shared__ float wsz[64 * WPAD];      // Wr_z transposed [i][o]
    __shared__ float rs[PROWS * WPAD];    // x rows
    const bool is_movie = (int)blockIdx.x < GM_BLOCKS;
    // movies: y feeds user-dst edges (et=1); z is dst term of movie-dst edges (et=0)
    const int et_y = is_movie ? 1 : 0;
    const int et_z = is_movie ? 0 : 1;
    const float* wly = wl + (layer * 2 + et_y) * 4096;
    const float* wrz = wr + (layer * 2 + et_z) * 4096;
    const float* blz = bl + (layer * 2 + et_z) * 64;
    const int nrows = is_movie ? M : U;
    const int x_off = is_movie ? xm_off : xu_off;
    const int z_off = is_movie ? OFF_ZM : OFF_ZU;
    __half* ytab    = is_movie ? g_hym : g_hyu;
    const int ntiles = (nrows + PROWS - 1) / PROWS;
    const int t0     = is_movie ? blockIdx.x : blockIdx.x - GM_BLOCKS;
    const int tstep  = is_movie ? GM_BLOCKS : GU_BLOCKS;
    int tid = threadIdx.x;

    // Load weights ONCE per block (amortized over ~10 tiles).
    for (int idx = tid; idx < 4096; idx += 256) {
        int o = idx >> 6, i = idx & 63;   // coalesced global read
        wsy[i * WPAD + o] = __ldg(wly + idx);
        wsz[i * WPAD + o] = __ldg(wrz + idx);
    }
    int og = tid & 15, rg = tid >> 4;     // 16 o-groups x 16 row-groups
    int o0 = og * 4, r0 = rg * 2;
    float4 bz = *(const float4*)(blz + o0);
    const unsigned long long zb_a = pack2(bz.x, bz.y), zb_b = pack2(bz.z, bz.w);
    const float4* x4 = (const float4*)(g_buf + x_off);
    float* z = g_buf + z_off;
    int ldr = tid >> 4, ldq = tid & 15;
    __syncthreads();

    for (int t = t0; t < ntiles; t += tstep) {
        const int row0 = t * PROWS;
        // load x tile (32 rows x 16 float4)
#pragma unroll
        for (int rr = ldr; rr < PROWS; rr += 16) {
            int g = row0 + rr;
            if (g < nrows) *(float4*)&rs[rr * WPAD + ldq * 4] = __ldg(x4 + g * 16 + ldq);
        }
        __syncthreads();

        unsigned long long y0a = 0ull, y0b = 0ull, y1a = 0ull, y1b = 0ull;
        unsigned long long z0a = zb_a, z0b = zb_b, z1a = zb_a, z1b = zb_b;
#pragma unroll 16
        for (int i = 0; i < 64; i++) {
            ulonglong2 wy = *(const ulonglong2*)&wsy[i * WPAD + o0];
            ulonglong2 wz = *(const ulonglong2*)&wsz[i * WPAD + o0];
            unsigned long long px0 = pack_dup(rs[r0 * WPAD + i]);
            unsigned long long px1 = pack_dup(rs[(r0 + 1) * WPAD + i]);
            ffma2(y0a, px0, wy.x); ffma2(y0b, px0, wy.y);
            ffma2(z0a, px0, wz.x); ffma2(z0b, px0, wz.y);
            ffma2(y1a, px1, wy.x); ffma2(y1b, px1, wy.y);
            ffma2(z1a, px1, wz.x); ffma2(z1b, px1, wz.y);
        }
        float2 y0xy = unpack2(y0a), y0zw = unpack2(y0b);
        float2 y1xy = unpack2(y1a), y1zw = unpack2(y1b);
        float2 z0xy = unpack2(z0a), z0zw = unpack2(z0b);
        float2 z1xy = unpack2(z1a), z1zw = unpack2(z1b);

        int g0 = row0 + r0;
        if (g0 < nrows) {
            *(float4*)(z + g0 * 64 + o0) = make_float4(z0xy.x, z0xy.y, z0zw.x, z0zw.y);
            uint2 p;
            ((__half2*)&p)[0] = __floats2half2_rn(y0xy.x, y0xy.y);
            ((__half2*)&p)[1] = __floats2half2_rn(y0zw.x, y0zw.y);
            *(uint2*)(ytab + g0 * 64 + o0) = p;
        }
        if (g0 + 1 < nrows) {
            *(float4*)(z + (g0 + 1) * 64 + o0) = make_float4(z1xy.x, z1xy.y, z1zw.x, z1zw.y);
            uint2 p;
            ((__half2*)&p)[0] = __floats2half2_rn(y1xy.x, y1xy.y);
            ((__half2*)&p)[1] = __floats2half2_rn(y1zw.x, y1zw.y);
            *(uint2*)(ytab + (g0 + 1) * 64 + o0) = p;
        }
        __syncthreads();   // rs reused next tile
    }
}

// ---------------------------------------------------------------------------
__device__ __forceinline__ void acc8(float* a, uint4 v) {
    float2 f;
    f = __half22float2(*(__half2*)&v.x); a[0] += f.x; a[1] += f.y;
    f = __half22float2(*(__half2*)&v.y); a[2] += f.x; a[3] += f.y;
    f = __half22float2(*(__half2*)&v.z); a[4] += f.x; a[5] += f.y;
    f = __half22float2(*(__half2*)&v.w); a[6] += f.x; a[7] += f.y;
}

// Gather-mean of fp16 y rows + z + optional relu -> x_new (fp32).
// 8 lanes per node (y row = 128 B = one cache line), unroll 8 (MLP=8).
__global__ void k_gather_add(int xm_out, int xu_out, int M, int U, int do_relu) {
    int t = blockIdx.x * blockDim.x + threadIdx.x;
    int node = t >> 3;
    if (node >= M + U) return;
    int lane = t & 7;
    bool is_movie = node < M;
    int local = is_movie ? node : node - M;
    const int pad = is_movie ? PAD_M : PAD_U;
    const int* bk = (is_movie ? g_bucket_m : g_bucket_u) + (long)local * pad;
    int dt = g_deg[(is_movie ? UQ : 0) + local];
    float iv = 1.f / fmaxf((float)dt, 1.f);
    int d = min(dt, pad);
    const uint4* y4 = (const uint4*)(is_movie ? g_hyu : g_hym);  // gather OTHER side's y

    float a[8]  = {0.f, 0.f, 0.f, 0.f, 0.f, 0.f, 0.f, 0.f};
    float a2[8] = {0.f, 0.f, 0.f, 0.f, 0.f, 0.f, 0.f, 0.f};
    int i = 0;
    for (; i + 8 <= d; i += 8) {
        int4 na = __ldg((const int4*)(bk + i));
        int4 nb = __ldg((const int4*)(bk + i + 4));
        uint4 v0 = __ldg(y4 + na.x * 8 + lane);
        uint4 v1 = __ldg(y4 + na.y * 8 + lane);
        uint4 v2 = __ldg(y4 + na.z * 8 + lane);
        uint4 v3 = __ldg(y4 + na.w * 8 + lane);
        uint4 v4 = __ldg(y4 + nb.x * 8 + lane);
        uint4 v5 = __ldg(y4 + nb.y * 8 + lane);
        uint4 v6 = __ldg(y4 + nb.z * 8 + lane);
        uint4 v7 = __ldg(y4 + nb.w * 8 + lane);
        acc8(a, v0); acc8(a, v1); acc8(a, v2); acc8(a, v3);
        acc8(a2, v4); acc8(a2, v5); acc8(a2, v6); acc8(a2, v7);
    }
    for (; i + 4 <= d; i += 4) {
        int4 na = __ldg((const int4*)(bk + i));
        uint4 v0 = __ldg(y4 + na.x * 8 + lane);
        uint4 v1 = __ldg(y4 + na.y * 8 + lane);
        uint4 v2 = __ldg(y4 + na.z * 8 + lane);
        uint4 v3 = __ldg(y4 + na.w * 8 + lane);
        acc8(a, v0); acc8(a, v1); acc8(a, v2); acc8(a, v3);
    }
    for (; i < d; i++) {
        int nb = __ldg(bk + i);
        acc8(a, __ldg(y4 + nb * 8 + lane));
    }
#pragma unroll
    for (int k = 0; k < 8; k++) a[k] += a2[k];
    const float4* zp = (const float4*)(g_buf + (is_movie ? OFF_ZM : OFF_ZU)) + local * 16 + lane * 2;
    float4 z0 = __ldg(zp), z1 = __ldg(zp + 1);
    float4 r0 = make_float4(fmaf(a[0], iv, z0.x), fmaf(a[1], iv, z0.y),
                            fmaf(a[2], iv, z0.z), fmaf(a[3], iv, z0.w));
    float4 r1 = make_float4(fmaf(a[4], iv, z1.x), fmaf(a[5], iv, z1.y),
                            fmaf(a[6], iv, z1.z), fmaf(a[7], iv, z1.w));
    if (do_relu) {
        r0.x = fmaxf(r0.x, 0.f); r0.y = fmaxf(r0.y, 0.f);
        r0.z = fmaxf(r0.z, 0.f); r0.w = fmaxf(r0.w, 0.f);
        r1.x = fmaxf(r1.x, 0.f); r1.y = fmaxf(r1.y, 0.f);
        r1.z = fmaxf(r1.z, 0.f); r1.w = fmaxf(r1.w, 0.f);
    }
    float4* o4 = (float4*)(g_buf + (is_movie ? xm_out : xu_out)) + local * 16 + lane * 2;
    o4[0] = r0;
    o4[1] = r1;
}

// out[l] = dot(x_u[label_src[l]], x_m[label_dst[l]]); one warp per label.
__global__ void k_labels(const int* __restrict__ ls, const int* __restrict__ ld,
                         int xu_off, int xm_off, float* __restrict__ out, int L) {
    int t = blockIdx.x * blockDim.x + threadIdx.x;
    int l = t >> 5;
    if (l >= L) return;
    int lane = t & 31;
    const float2* xu = (const float2*)(g_buf + xu_off);
    const float2* xm = (const float2*)(g_buf + xm_off);
    int s = __ldg(ls + l), d = __ldg(ld + l);
    float2 a = __ldg(xu + s * 32 + lane);
    float2 b = __ldg(xm + d * 32 + lane);
    float v = fmaf(a.x, b.x, a.y * b.y);
#pragma unroll
    for (int off = 16; off; off >>= 1) v += __shfl_xor_sync(0xffffffffu, v, off);
    if (lane == 0) out[l] = v;
}

// ---------------------------------------------------------------------------
extern "C" void kernel_launch(void* const* d_in, const int* in_sizes, int n_in,
                              void* d_out, int out_size) {
    const float* movie_x   = (const float*)d_in[0];
    const float* user_emb  = (const float*)d_in[1];
    const float* movie_emb = (const float*)d_in[2];
    const float* mw        = (const float*)d_in[3];
    const float* mb        = (const float*)d_in[4];
    const float* wl        = (const float*)d_in[5];
    const float* blb       = (const float*)d_in[6];
    const float* wr        = (const float*)d_in[7];
    const int*   es        = (const int*)d_in[8];
    const int*   ed        = (const int*)d_in[9];
    const int*   ls        = (const int*)d_in[10];
    const int*   ld        = (const int*)d_in[11];
    float* out = (float*)d_out;

    const int U = in_sizes[1] / HH;
    const int M = in_sizes[2] / HH;
    const int E = in_sizes[8];
    const int L = in_sizes[10];
    const int TB = 256;

    // launch 1: zero degree counters
    k_zero_deg<<<(U + M + TB - 1) / TB, TB>>>(U + M);
    // launch 2: fused feature init (movies projected, users copied)
    const int MB4 = (M + 3) / 4;
    const int UBc = (U * 16 + TB - 1) / TB;
    k_init<<<MB4 + UBc, TB>>>((const float4*)user_emb, movie_x, mw, mb, movie_emb,
                              MB4, M, U);
    // launch 3: adjacency buckets (+degree counting)
    k_fill<<<(E + TB - 1) / TB, TB>>>(es, ed, E);

    const int GAB = (int)(((long)(M + U) * 8 + TB - 1) / TB);
    for (int layer = 0; layer < 2; layer++) {
        const int xu_in  = layer ? OFF_XU1 : OFF_XU0;
        const int xm_in  = layer ? OFF_XM1 : OFF_XM0;
        const int xu_out = layer ? OFF_XU0 : OFF_XU1;
        const int xm_out = layer ? OFF_XM0 : OFF_XM1;

        // launch 4 (profiled on layer 0): dense pre-transform y,z (persistent tiles)
        k_pre<<<GM_BLOCKS + GU_BLOCKS, 256>>>(xm_in, xu_in, wl, blb, wr, layer, M, U);
        // gather-mean(y) + z (+relu)
        k_gather_add<<<GAB, TB>>>(xm_out, xu_out, M, U, layer == 0);
    }

    // final features are in the *0 buffers
    long lt = (long)L * 32;
    k_labels<<<(int)((lt + TB - 1) / TB), TB>>>(ls, ld, OFF_XU0, OFF_XM0, out, L);
}

// round 11
// speedup vs baseline: 1.9319x; 1.0585x over previous
#include <cuda_runtime.h>
#include <cuda_fp16.h>

// Problem constants (shapes fixed by the dataset)
#define UQ 100000          // users
#define MQ 50000           // movies
#define HH 64              // hidden dim
#define UN (UQ*HH)
#define MN (MQ*HH)
#define PAD_U 64           // max user degree slots (Poisson(20) tail safe)
#define PAD_M 128          // max movie degree slots (Poisson(40) tail safe)

// Scratch layout inside one big __device__ buffer (offsets in floats)
#define OFF_XU0  0
#define OFF_XU1  (OFF_XU0 + UN)
#define OFF_XM0  (OFF_XU1 + UN)
#define OFF_XM1  (OFF_XM0 + MN)
#define OFF_ZU   (OFF_XM1 + MN)      // z_u = x_u @ Wr^T + b   [U,64] fp32
#define OFF_ZM   (OFF_ZU + UN)       // z_m = x_m @ Wr^T + b   [M,64] fp32
#define TOTAL_F  (OFF_ZM + MN)

__device__ __align__(16) float g_buf[TOTAL_F];        // ~115 MB scratch
__device__ int g_deg[UQ + MQ];                        // users then movies (fill cursors)
__device__ __align__(16) int g_bucket_u[UQ * PAD_U];  // movie ids per user
__device__ __align__(16) int g_bucket_m[MQ * PAD_M];  // user ids per movie
__device__ __align__(16) __half g_hyu[UN];            // y_u = x_u @ Wl[l,0]^T (fp16)
__device__ __align__(16) __half g_hym[MN];            // y_m = x_m @ Wl[l,1]^T (fp16)

// ---------------------------------------------------------------------------
// Packed f32x2 helpers (Blackwell sm_103a FFMA2 path)
__device__ __forceinline__ unsigned long long pack_dup(float x) {
    unsigned long long r;
    asm("mov.b64 %0, {%1, %1};" : "=l"(r) : "f"(x));
    return r;
}
__device__ __forceinline__ unsigned long long pack2(float a, float b) {
    unsigned long long r;
    asm("mov.b64 %0, {%1, %2};" : "=l"(r) : "f"(a), "f"(b));
    return r;
}
__device__ __forceinline__ void ffma2(unsigned long long& d,
                                      unsigned long long a, unsigned long long b) {
    asm("fma.rn.f32x2 %0, %1, %2, %0;" : "+l"(d) : "l"(a), "l"(b));
}
__device__ __forceinline__ float2 unpack2(unsigned long long v) {
    float2 f;
    asm("mov.b64 {%0, %1}, %2;" : "=f"(f.x), "=f"(f.y) : "l"(v));
    return f;
}

// ---------------------------------------------------------------------------
__global__ void k_zero_deg(int n) {
    int i = blockIdx.x * blockDim.x + threadIdx.x;
    if (i < n) g_deg[i] = 0;
}

// Fused init: movie blocks compute x_m0 = movie_x @ W.T + b + movie_emb
// (4 rows/block, 256 thr); user blocks copy user_emb into g_buf.
__global__ void __launch_bounds__(256)
k_init(const float4* __restrict__ uemb,
       const float* __restrict__ mx, const float* __restrict__ w,
       const float* __restrict__ b, const float* __restrict__ memb,
       int MB4, int M, int U) {
    int tid = threadIdx.x;
    if ((int)blockIdx.x < MB4) {
        __shared__ float xs[4][20];
        int r = tid >> 6, o = tid & 63;
        int row = blockIdx.x * 4 + r;
        if (tid < 80) {
            int rr = tid / 20, cc = tid % 20;
            int g = blockIdx.x * 4 + rr;
            if (g < M) xs[rr][cc] = __ldg(mx + g * 20 + cc);
        }
        __syncthreads();
        if (row < M) {
            float acc = __ldg(b + o) + __ldg(memb + row * 64 + o);
#pragma unroll
            for (int k = 0; k < 20; k++) acc = fmaf(xs[r][k], __ldg(w + o * 20 + k), acc);
            g_buf[OFF_XM0 + row * 64 + o] = acc;
        }
    } else {
        int i = ((int)blockIdx.x - MB4) * 256 + tid;
        if (i < U * 16) ((float4*)(g_buf + OFF_XU0))[i] = __ldg(uemb + i);
    }
}

// Bucket fill: degree counting and slot allocation in one pass over edges.
__global__ void k_fill(const int* __restrict__ es, const int* __restrict__ ed, int E) {
    int e = blockIdx.x * blockDim.x + threadIdx.x;
    if (e >= E) return;
    int u = __ldg(es + e), m = __ldg(ed + e);
    int su = atomicAdd(&g_deg[u], 1);
    if (su < PAD_U) g_bucket_u[u * PAD_U + su] = m;
    int sm = atomicAdd(&g_deg[UQ + m], 1);
    if (sm < PAD_M) g_bucket_m[m * PAD_M + sm] = u;
}

// ---------------------------------------------------------------------------
// Pre-transform (dense, per node): y = x @ Wl_y^T (fp16 out, feeds the gather),
// z = x @ Wr_z^T + b (fp32, dst-side term).
// PERSISTENT TILES: each block loads its weights ONCE (y-weights stored fp16 in
// smem -> 1 wavefront/warp-i; math stays fp32 via FFMA2), then grid-strides.
#define PROWS 32
#define WPAD 68            // fp32 weight row stride (floats)
#define WPADH 68           // fp16 weight row stride (halves)
#define GM_BLOCKS 296      // movie-segment blocks (2 per SM)
#define GU_BLOCKS 592      // user-segment blocks (4 per SM)
__global__ void __launch_bounds__(256)
k_pre(int xm_off, int xu_off, const float* __restrict__ wl,
      const float* __restrict__ bl, const float* __restrict__ wr,
      int layer, int M, int U) {
    __shared__ __half wsy[64 * WPADH];    // Wl_y transposed [i][o], fp16
    __shared__ float  wsz[64 * WPAD];     // Wr_z transposed [i][o], fp32
    __shared__ float  rs[PROWS * WPAD];   // x rows
    const bool is_movie = (int)blockIdx.x < GM_BLOCKS;
    // movies: y feeds user-dst edges (et=1); z is dst term of movie-dst edges (et=0)
    const int et_y = is_movie ? 1 : 0;
    const int et_z = is_movie ? 0 : 1;
    const float* wly = wl + (layer * 2 + et_y) * 4096;
    const float* wrz = wr + (layer * 2 + et_z) * 4096;
    const float* blz = bl + (layer * 2 + et_z) * 64;
    const int nrows = is_movie ? M : U;
    const int x_off = is_movie ? xm_off : xu_off;
    const int z_off = is_movie ? OFF_ZM : OFF_ZU;
    __half* ytab    = is_movie ? g_hym : g_hyu;
    const int ntiles = (nrows + PROWS - 1) / PROWS;
    const int t0     = is_movie ? blockIdx.x : blockIdx.x - GM_BLOCKS;
    const int tstep  = is_movie ? GM_BLOCKS : GU_BLOCKS;
    int tid = threadIdx.x;

    // Load weights ONCE per block.
    for (int idx = tid; idx < 4096; idx += 256) {
        int o = idx >> 6, i = idx & 63;   // coalesced global read
        wsy[i * WPADH + o] = __float2half_rn(__ldg(wly + idx));
        wsz[i * WPAD + o]  = __ldg(wrz + idx);
    }
    int og = tid & 15, rg = tid >> 4;     // 16 o-groups x 16 row-groups
    int o0 = og * 4, r0 = rg * 2;
    float4 bz = *(const float4*)(blz + o0);
    const unsigned long long zb_a = pack2(bz.x, bz.y), zb_b = pack2(bz.z, bz.w);
    const float4* x4 = (const float4*)(g_buf + x_off);
    float* z = g_buf + z_off;
    int ldr = tid >> 4, ldq = tid & 15;
    __syncthreads();

    for (int t = t0; t < ntiles; t += tstep) {
        const int row0 = t * PROWS;
        // load x tile (32 rows x 16 float4)
#pragma unroll
        for (int rr = ldr; rr < PROWS; rr += 16) {
            int g = row0 + rr;
            if (g < nrows) *(float4*)&rs[rr * WPAD + ldq * 4] = __ldg(x4 + g * 16 + ldq);
        }
        __syncthreads();

        unsigned long long y0a = 0ull, y0b = 0ull, y1a = 0ull, y1b = 0ull;
        unsigned long long z0a = zb_a, z0b = zb_b, z1a = zb_a, z1b = zb_b;
#pragma unroll 16
        for (int i = 0; i < 64; i++) {
            uint2 wyh = *(const uint2*)&wsy[i * WPADH + o0];           // 4 halves, LDS.64
            ulonglong2 wz = *(const ulonglong2*)&wsz[i * WPAD + o0];   // 4 floats, LDS.128
            float2 wy01 = __half22float2(*(__half2*)&wyh.x);
            float2 wy23 = __half22float2(*(__half2*)&wyh.y);
            unsigned long long wya = pack2(wy01.x, wy01.y);
            unsigned long long wyb = pack2(wy23.x, wy23.y);
            unsigned long long px0 = pack_dup(rs[r0 * WPAD + i]);
            unsigned long long px1 = pack_dup(rs[(r0 + 1) * WPAD + i]);
            ffma2(y0a, px0, wya); ffma2(y0b, px0, wyb);
            ffma2(z0a, px0, wz.x); ffma2(z0b, px0, wz.y);
            ffma2(y1a, px1, wya); ffma2(y1b, px1, wyb);
            ffma2(z1a, px1, wz.x); ffma2(z1b, px1, wz.y);
        }
        float2 y0xy = unpack2(y0a), y0zw = unpack2(y0b);
        float2 y1xy = unpack2(y1a), y1zw = unpack2(y1b);
        float2 z0xy = unpack2(z0a), z0zw = unpack2(z0b);
        float2 z1xy = unpack2(z1a), z1zw = unpack2(z1b);

        int g0 = row0 + r0;
        if (g0 < nrows) {
            *(float4*)(z + g0 * 64 + o0) = make_float4(z0xy.x, z0xy.y, z0zw.x, z0zw.y);
            uint2 p;
            ((__half2*)&p)[0] = __floats2half2_rn(y0xy.x, y0xy.y);
            ((__half2*)&p)[1] = __floats2half2_rn(y0zw.x, y0zw.y);
            *(uint2*)(ytab + g0 * 64 + o0) = p;
        }
        if (g0 + 1 < nrows) {
            *(float4*)(z + (g0 + 1) * 64 + o0) = make_float4(z1xy.x, z1xy.y, z1zw.x, z1zw.y);
            uint2 p;
            ((__half2*)&p)[0] = __floats2half2_rn(y1xy.x, y1xy.y);
            ((__half2*)&p)[1] = __floats2half2_rn(y1zw.x, y1zw.y);
            *(uint2*)(ytab + (g0 + 1) * 64 + o0) = p;
        }
        __syncthreads();   // rs reused next tile
    }
}

// ---------------------------------------------------------------------------
__device__ __forceinline__ void acc8(float* a, uint4 v) {
    float2 f;
    f = __half22float2(*(__half2*)&v.x); a[0] += f.x; a[1] += f.y;
    f = __half22float2(*(__half2*)&v.y); a[2] += f.x; a[3] += f.y;
    f = __half22float2(*(__half2*)&v.z); a[4] += f.x; a[5] += f.y;
    f = __half22float2(*(__half2*)&v.w); a[6] += f.x; a[7] += f.y;
}

// Gather-mean of fp16 y rows + z + optional relu -> x_new (fp32).
// 8 lanes per node (y row = 128 B = one cache line), unroll 8 (MLP=8).
__global__ void k_gather_add(int xm_out, int xu_out, int M, int U, int do_relu) {
    int t = blockIdx.x * blockDim.x + threadIdx.x;
    int node = t >> 3;
    if (node >= M + U) return;
    int lane = t & 7;
    bool is_movie = node < M;
    int local = is_movie ? node : node - M;
    const int pad = is_movie ? PAD_M : PAD_U;
    const int* bk = (is_movie ? g_bucket_m : g_bucket_u) + (long)local * pad;
    int dt = g_deg[(is_movie ? UQ : 0) + local];
    float iv = 1.f / fmaxf((float)dt, 1.f);
    int d = min(dt, pad);
    const uint4* y4 = (const uint4*)(is_movie ? g_hyu : g_hym);  // gather OTHER side's y

    float a[8]  = {0.f, 0.f, 0.f, 0.f, 0.f, 0.f, 0.f, 0.f};
    float a2[8] = {0.f, 0.f, 0.f, 0.f, 0.f, 0.f, 0.f, 0.f};
    int i = 0;
    for (; i + 8 <= d; i += 8) {
        int4 na = __ldg((const int4*)(bk + i));
        int4 nb = __ldg((const int4*)(bk + i + 4));
        uint4 v0 = __ldg(y4 + na.x * 8 + lane);
        uint4 v1 = __ldg(y4 + na.y * 8 + lane);
        uint4 v2 = __ldg(y4 + na.z * 8 + lane);
        uint4 v3 = __ldg(y4 + na.w * 8 + lane);
        uint4 v4 = __ldg(y4 + nb.x * 8 + lane);
        uint4 v5 = __ldg(y4 + nb.y * 8 + lane);
        uint4 v6 = __ldg(y4 + nb.z * 8 + lane);
        uint4 v7 = __ldg(y4 + nb.w * 8 + lane);
        acc8(a, v0); acc8(a, v1); acc8(a, v2); acc8(a, v3);
        acc8(a2, v4); acc8(a2, v5); acc8(a2, v6); acc8(a2, v7);
    }
    for (; i + 4 <= d; i += 4) {
        int4 na = __ldg((const int4*)(bk + i));
        uint4 v0 = __ldg(y4 + na.x * 8 + lane);
        uint4 v1 = __ldg(y4 + na.y * 8 + lane);
        uint4 v2 = __ldg(y4 + na.z * 8 + lane);
        uint4 v3 = __ldg(y4 + na.w * 8 + lane);
        acc8(a, v0); acc8(a, v1); acc8(a, v2); acc8(a, v3);
    }
    for (; i < d; i++) {
        int nb = __ldg(bk + i);
        acc8(a, __ldg(y4 + nb * 8 + lane));
    }
#pragma unroll
    for (int k = 0; k < 8; k++) a[k] += a2[k];
    const float4* zp = (const float4*)(g_buf + (is_movie ? OFF_ZM : OFF_ZU)) + local * 16 + lane * 2;
    float4 z0 = __ldg(zp), z1 = __ldg(zp + 1);
    float4 r0 = make_float4(fmaf(a[0], iv, z0.x), fmaf(a[1], iv, z0.y),
                            fmaf(a[2], iv, z0.z), fmaf(a[3], iv, z0.w));
    float4 r1 = make_float4(fmaf(a[4], iv, z1.x), fmaf(a[5], iv, z1.y),
                            fmaf(a[6], iv, z1.z), fmaf(a[7], iv, z1.w));
    if (do_relu) {
        r0.x = fmaxf(r0.x, 0.f); r0.y = fmaxf(r0.y, 0.f);
        r0.z = fmaxf(r0.z, 0.f); r0.w = fmaxf(r0.w, 0.f);
        r1.x = fmaxf(r1.x, 0.f); r1.y = fmaxf(r1.y, 0.f);
        r1.z = fmaxf(r1.z, 0.f); r1.w = fmaxf(r1.w, 0.f);
    }
    float4* o4 = (float4*)(g_buf + (is_movie ? xm_out : xu_out)) + local * 16 + lane * 2;
    o4[0] = r0;
    o4[1] = r1;
}

// out[l] = dot(x_u[label_src[l]], x_m[label_dst[l]]); one warp per label.
__global__ void k_labels(const int* __restrict__ ls, const int* __restrict__ ld,
                         int xu_off, int xm_off, float* __restrict__ out, int L) {
    int t = blockIdx.x * blockDim.x + threadIdx.x;
    int l = t >> 5;
    if (l >= L) return;
    int lane = t & 31;
    const float2* xu = (const float2*)(g_buf + xu_off);
    const float2* xm = (const float2*)(g_buf + xm_off);
    int s = __ldg(ls + l), d = __ldg(ld + l);
    float2 a = __ldg(xu + s * 32 + lane);
    float2 b = __ldg(xm + d * 32 + lane);
    float v = fmaf(a.x, b.x, a.y * b.y);
#pragma unroll
    for (int off = 16; off; off >>= 1) v += __shfl_xor_sync(0xffffffffu, v, off);
    if (lane == 0) out[l] = v;
}

// ---------------------------------------------------------------------------
extern "C" void kernel_launch(void* const* d_in, const int* in_sizes, int n_in,
                              void* d_out, int out_size) {
    const float* movie_x   = (const float*)d_in[0];
    const float* user_emb  = (const float*)d_in[1];
    const float* movie_emb = (const float*)d_in[2];
    const float* mw        = (const float*)d_in[3];
    const float* mb        = (const float*)d_in[4];
    const float* wl        = (const float*)d_in[5];
    const float* blb       = (const float*)d_in[6];
    const float* wr        = (const float*)d_in[7];
    const int*   es        = (const int*)d_in[8];
    const int*   ed        = (const int*)d_in[9];
    const int*   ls        = (const int*)d_in[10];
    const int*   ld        = (const int*)d_in[11];
    float* out = (float*)d_out;

    const int U = in_sizes[1] / HH;
    const int M = in_sizes[2] / HH;
    const int E = in_sizes[8];
    const int L = in_sizes[10];
    const int TB = 256;

    // launch 1: zero degree counters
    k_zero_deg<<<(U + M + TB - 1) / TB, TB>>>(U + M);
    // launch 2: fused feature init (movies projected, users copied)
    const int MB4 = (M + 3) / 4;
    const int UBc = (U * 16 + TB - 1) / TB;
    k_init<<<MB4 + UBc, TB>>>((const float4*)user_emb, movie_x, mw, mb, movie_emb,
                              MB4, M, U);
    // launch 3: adjacency buckets (+degree counting)
    k_fill<<<(E + TB - 1) / TB, TB>>>(es, ed, E);

    const int GAB = (int)(((long)(M + U) * 8 + TB - 1) / TB);
    for (int layer = 0; layer < 2; layer++) {
        const int xu_in  = layer ? OFF_XU1 : OFF_XU0;
        const int xm_in  = layer ? OFF_XM1 : OFF_XM0;
        const int xu_out = layer ? OFF_XU0 : OFF_XU1;
        const int xm_out = layer ? OFF_XM0 : OFF_XM1;

        // launch 4 (profiled on layer 0): dense pre-transform y,z (persistent tiles)
        k_pre<<<GM_BLOCKS + GU_BLOCKS, 256>>>(xm_in, xu_in, wl, blb, wr, layer, M, U);
        // gather-mean(y) + z (+relu)
        k_gather_add<<<GAB, TB>>>(xm_out, xu_out, M, U, layer == 0);
    }

    // final features are in the *0 buffers
    long lt = (long)L * 32;
    k_labels<<<(int)((lt + TB - 1) / TB), TB>>>(ls, ld, OFF_XU0, OFF_XM0, out, L);
}